// round 16
// baseline (speedup 1.0000x reference)
#include <cuda_runtime.h>
#include <cuda_fp16.h>
#include <cstdint>

#define B_SZ   8
#define T_SEQ  1023
#define C_DIM  1024
#define H_NUM  16
#define DK     64
#define R_ROWS (B_SZ * T_SEQ)   // 8184
#define LOG2E  1.4426950408889634f

// ---------------- scratch (__device__ globals: allocation-free contract) ----
__device__ __half g_xb [(size_t)R_ROWS * C_DIM];   // x fp16
__device__ __half g_qb [(size_t)R_ROWS * C_DIM];   // relu_out fp16 (Q)
__device__ __half g_vs [(size_t)R_ROWS * C_DIM];   // value fp16
__device__ __half g_yh [(size_t)R_ROWS * C_DIM];   // attn out fp16
__device__ __half g_w1s[(size_t)C_DIM * C_DIM];
__device__ __half g_vws[(size_t)C_DIM * C_DIM];
__device__ __half g_pws[(size_t)C_DIM * C_DIM];
__device__ __half g_w2t[(size_t)1024 * DK];        // w2^T * log2e, fp16, padded
__device__ float  g_scs[(size_t)B_SZ * H_NUM * 8 * DK];  // per-(b,h,tile) V colsums

// ---------------- tensor-core helpers (base-target sm_80+ class) -----------
__device__ __forceinline__ uint32_t smem_to_u32(const void* p) {
    uint32_t a;
    asm("{ .reg .u64 t; cvta.to.shared.u64 t, %1; cvt.u32.u64 %0, t; }"
        : "=r"(a) : "l"(p));
    return a;
}
__device__ __forceinline__ void ldsm_x4(uint32_t& r0, uint32_t& r1,
                                        uint32_t& r2, uint32_t& r3, uint32_t addr) {
    asm volatile("ldmatrix.sync.aligned.m8n8.x4.shared.b16 {%0,%1,%2,%3}, [%4];"
                 : "=r"(r0), "=r"(r1), "=r"(r2), "=r"(r3) : "r"(addr));
}
__device__ __forceinline__ void ldsm_x4_t(uint32_t& r0, uint32_t& r1,
                                          uint32_t& r2, uint32_t& r3, uint32_t addr) {
    asm volatile("ldmatrix.sync.aligned.m8n8.x4.trans.shared.b16 {%0,%1,%2,%3}, [%4];"
                 : "=r"(r0), "=r"(r1), "=r"(r2), "=r"(r3) : "r"(addr));
}
__device__ __forceinline__ void mma_f16(float* c, const uint32_t* a, const uint32_t* b) {
    asm volatile(
        "mma.sync.aligned.m16n8k16.row.col.f32.f16.f16.f32 "
        "{%0,%1,%2,%3}, {%4,%5,%6,%7}, {%8,%9}, {%0,%1,%2,%3};"
        : "+f"(c[0]), "+f"(c[1]), "+f"(c[2]), "+f"(c[3])
        : "r"(a[0]), "r"(a[1]), "r"(a[2]), "r"(a[3]), "r"(b[0]), "r"(b[1]));
}
__device__ __forceinline__ uint32_t pack_f16(float lo, float hi) {
    uint32_t r;
    asm("cvt.rn.f16x2.f32 %0, %1, %2;" : "=r"(r) : "f"(hi), "f"(lo));
    return r;
}
__device__ __forceinline__ float ex2f(float x) {
    float r;
    asm("ex2.approx.f32 %0, %1;" : "=f"(r) : "f"(x));
    return r;
}
__device__ __forceinline__ void cp16(uint32_t saddr, const void* gaddr) {
    asm volatile("cp.async.cg.shared.global [%0], [%1], 16;"
                 :: "r"(saddr), "l"(gaddr));
}
#define CP_COMMIT() asm volatile("cp.async.commit_group;")
template<int N>
__device__ __forceinline__ void cp_wait() {
    asm volatile("cp.async.wait_group %0;" :: "n"(N));
}

// ---------------------------------------------------------------------------
// conversions / prep
// ---------------------------------------------------------------------------
__global__ void cvt_h(const float* __restrict__ in, __half* __restrict__ out, int n)
{
    int i = (blockIdx.x * blockDim.x + threadIdx.x) * 4;
    if (i < n) {
        float4 v = *(const float4*)(in + i);
        __half2 a, b;
        a.x = __float2half_rn(v.x); a.y = __float2half_rn(v.y);
        b.x = __float2half_rn(v.z); b.y = __float2half_rn(v.w);
        *(__half2*)(out + i)     = a;
        *(__half2*)(out + i + 2) = b;
    }
}

__global__ void cvt_h3(const float* __restrict__ i0, const float* __restrict__ i1,
                       const float* __restrict__ i2, __half* __restrict__ o0,
                       __half* __restrict__ o1, __half* __restrict__ o2)
{
    const float* in  = (blockIdx.y == 0) ? i0 : (blockIdx.y == 1) ? i1 : i2;
    __half*      out = (blockIdx.y == 0) ? o0 : (blockIdx.y == 1) ? o1 : o2;
    int i = (blockIdx.x * blockDim.x + threadIdx.x) * 4;
    float4 v = *(const float4*)(in + i);
    __half2 a, b;
    a.x = __float2half_rn(v.x); a.y = __float2half_rn(v.y);
    b.x = __float2half_rn(v.z); b.y = __float2half_rn(v.w);
    *(__half2*)(out + i)     = a;
    *(__half2*)(out + i + 2) = b;
}

// w2 [DK][T_SEQ] f32 -> w2t [1024][DK] fp16, PRESCALED by log2e.
__global__ void prep_w2t(const float* __restrict__ w2, __half* __restrict__ w2t)
{
    int idx = blockIdx.x * 256 + threadIdx.x;     // 1024*64
    int s = idx >> 6, d = idx & 63;
    float v = (s < T_SEQ) ? w2[d * T_SEQ + s] * LOG2E : 0.f;
    w2t[idx] = __float2half_rn(v);
}

// per-(b,h,tile) V column sums (same row clamping as attn's sV loads).
__global__ void v_colsum(const __half* __restrict__ V, float* __restrict__ Scs)
{
    int t = blockIdx.x, h = blockIdx.y, b = blockIdx.z, d = threadIdx.x;
    float s = 0.f;
    #pragma unroll 8
    for (int i = 0; i < 128; i++) {
        int sidx = t * 128 + i; if (sidx > T_SEQ - 1) sidx = T_SEQ - 1;
        s += __half2float(V[((size_t)b * T_SEQ + sidx) * C_DIM + h * DK + d]);
    }
    Scs[(((size_t)b * H_NUM + h) * 8 + t) * DK + d] = s;
}

// ---------------------------------------------------------------------------
// fp16 HMMA GEMM v3: CTA 128x128, FOUR warps as 2(m)x2(n), warp tile 64x64.
// 8 LDSM : 32 MMA per k16 (128 B/MMA smem traffic, was 192).
// cp.async double-buffered; 128 threads; 2 CTAs/SM (8 warps, 2 indep barriers).
// ---------------------------------------------------------------------------
#define BM  128
#define BN  128
#define BK  64
#define LDS 72
#define TILE_ELEMS (BM * LDS)
#define GSMEM (4 * TILE_ELEMS * 2)            // 2 x (A + B): 73728 bytes

// MODE 0: f32 out (+bias). MODE 1 (qv-fused): relu->fp16 / plain fp16.
template<int MODE>
__global__ __launch_bounds__(128, 2)
void gemm_db(const __half* __restrict__ A0,
             const __half* __restrict__ B0, const __half* __restrict__ B1,
             const float* __restrict__ bias0, const float* __restrict__ bias1,
             float* __restrict__ Of, __half* __restrict__ O0,
             __half* __restrict__ O1, int R)
{
    extern __shared__ __half sm[];

    const int  tid  = threadIdx.x;
    const int  wid  = tid >> 5;
    const int  lane = tid & 31;
    const int  wm   = wid >> 1;        // 0..1
    const int  wn   = wid & 1;         // 0..1
    const int  m0   = blockIdx.y * BM;
    const bool isQ  = (MODE == 1) && (blockIdx.x < 8);
    const int  n0   = (MODE == 1 ? (isQ ? blockIdx.x : blockIdx.x - 8)
                                 : blockIdx.x) * BN;
    const __half* Bsrc = (MODE == 1) ? (isQ ? B0 : B1) : B0;
    const float*  bias = (MODE == 1) ? (isQ ? bias0 : bias1) : bias0;

    const uint32_t sb = smem_to_u32(sm);
    const int lrow = tid >> 3;          // 0..15
    const int lc8  = (tid & 7) * 8;

    auto issue = [&](int k0, int buf) {
        const uint32_t dA = sb + (uint32_t)(buf * 2 * TILE_ELEMS) * 2;
        const uint32_t dB = dA + (uint32_t)TILE_ELEMS * 2;
        #pragma unroll
        for (int i = 0; i < 8; i++) {
            int row = lrow + i * 16;
            uint32_t so = (uint32_t)(row * LDS + lc8) * 2;
            int ar = m0 + row; if (ar > R - 1) ar = R - 1;   // clamp: epilogue guards
            cp16(dA + so, A0 + (size_t)ar * C_DIM + k0 + lc8);
            cp16(dB + so, Bsrc + (size_t)(n0 + row) * C_DIM + k0 + lc8);
        }
    };

    float acc[4][8][4];
    #pragma unroll
    for (int f = 0; f < 4; f++)
        #pragma unroll
        for (int j = 0; j < 8; j++)
            #pragma unroll
            for (int e = 0; e < 4; e++) acc[f][j][e] = 0.f;

    const int a_r = wm * 64 + (lane & 15);
    const int b_r = wn * 64 + (lane & 15);
    const int l_c = (lane >> 4) << 3;

    issue(0, 0);
    CP_COMMIT();

    for (int kc = 0; kc < C_DIM / BK; kc++) {
        const int p = kc & 1;
        if (kc < C_DIM / BK - 1) {
            issue((kc + 1) * BK, 1 - p);
            CP_COMMIT();
            cp_wait<1>();
        } else {
            cp_wait<0>();
        }
        __syncthreads();

        const uint32_t sbA = sb + (uint32_t)(p * 2 * TILE_ELEMS) * 2;
        const uint32_t sbB = sbA + (uint32_t)TILE_ELEMS * 2;

        #pragma unroll
        for (int kk = 0; kk < BK; kk += 16) {
            uint32_t af[4][4], bf[4][4];
            #pragma unroll
            for (int g = 0; g < 4; g++) {
                uint32_t off = (uint32_t)((b_r + g * 16) * LDS + kk + l_c) * 2;
                ldsm_x4(bf[g][0], bf[g][1], bf[g][2], bf[g][3], sbB + off);
            }
            #pragma unroll
            for (int f = 0; f < 4; f++) {
                uint32_t off = (uint32_t)((a_r + f * 16) * LDS + kk + l_c) * 2;
                ldsm_x4(af[f][0], af[f][1], af[f][2], af[f][3], sbA + off);
            }
            #pragma unroll
            for (int f = 0; f < 4; f++)
                #pragma unroll
                for (int g = 0; g < 4; g++) {
                    uint32_t blo[2] = { bf[g][0], bf[g][2] };
                    uint32_t bhi[2] = { bf[g][1], bf[g][3] };
                    mma_f16(acc[f][2 * g],     af[f], blo);
                    mma_f16(acc[f][2 * g + 1], af[f], bhi);
                }
        }
        __syncthreads();
    }

    const int qr = lane >> 2;
    const int qc = (lane & 3) * 2;
    #pragma unroll
    for (int f = 0; f < 4; f++) {
        #pragma unroll
        for (int j = 0; j < 8; j++) {
            int col = n0 + wn * 64 + j * 8 + qc;
            float b0 = bias[col], b1v = bias[col + 1];
            #pragma unroll
            for (int half = 0; half < 2; half++) {
                int row = m0 + wm * 64 + f * 16 + qr + half * 8;
                if (row < R) {
                    float v0 = acc[f][j][half * 2 + 0] + b0;
                    float v1 = acc[f][j][half * 2 + 1] + b1v;
                    if (MODE == 0) {
                        *(float2*)&Of[(size_t)row * C_DIM + col] = make_float2(v0, v1);
                    } else {
                        if (isQ) { v0 = fmaxf(v0, 0.f); v1 = fmaxf(v1, 0.f); }
                        __half* O = isQ ? O0 : O1;
                        __half2 hp;
                        hp.x = __float2half_rn(v0); hp.y = __float2half_rn(v1);
                        *(__half2*)&O[(size_t)row * C_DIM + col] = hp;
                    }
                }
            }
        }
    }
}

// ---------------------------------------------------------------------------
// HMMA fp16 flash attention v4 (R15 structure, unchanged).
// ---------------------------------------------------------------------------
#define ATE   (128 * LDS)
#define ASMEM (5 * ATE * 2 + 1024 * 4 + 64 * 4)
#define ONE2  0x3C003C00u                     // fp16 (1.0, 1.0)

template<bool DIAG>
__device__ __forceinline__ void attn_tile(
    uint32_t sbK, uint32_t sbV, int s0, const float* __restrict__ sb2a,
    const uint32_t (&qf)[4][4], float (&yacc)[8][4], float (&lacc)[4],
    int trow0, int c0l, int lgo, int lr16)
{
    const uint32_t ones2[2] = { ONE2, ONE2 };
    #pragma unroll
    for (int j = 0; j < 8; j++) {
        float Sp[2][4];
        #pragma unroll
        for (int fh = 0; fh < 2; fh++) {
            float2 bb2 = *(const float2*)&sb2a[s0 + 8 * (2 * j + fh) + c0l];
            Sp[fh][0] = bb2.x; Sp[fh][1] = bb2.y;
            Sp[fh][2] = bb2.x; Sp[fh][3] = bb2.y;
        }

        int nr = j * 16 + lr16;
        #pragma unroll
        for (int k = 0; k < 4; k++) {
            uint32_t bb[4];
            ldsm_x4(bb[0], bb[1], bb[2], bb[3],
                    sbK + (uint32_t)(nr * LDS + k * 16 + lgo) * 2);
            uint32_t blo[2] = { bb[0], bb[2] };
            uint32_t bhi[2] = { bb[1], bb[3] };
            mma_f16(Sp[0], qf[k], blo);
            mma_f16(Sp[1], qf[k], bhi);
        }

        float pv_[2][4];
        #pragma unroll
        for (int fh = 0; fh < 2; fh++) {
            if (!DIAG) {
                #pragma unroll
                for (int e = 0; e < 4; e++)
                    pv_[fh][e] = ex2f(Sp[fh][e]) - 1.f;
            } else {
                int f = 2 * j + fh;
                #pragma unroll
                for (int e = 0; e < 4; e++) {
                    int col = 8 * f + c0l + (e & 1);
                    int rr  = trow0 + ((e >> 1) << 3);
                    bool ok = (s0 + col <= rr);
                    pv_[fh][e] = ok ? (ex2f(Sp[fh][e]) - 1.f) : -1.f;
                }
            }
        }

        uint32_t Ah_[4];
        #pragma unroll
        for (int fh = 0; fh < 2; fh++) {
            Ah_[2 * fh + 0] = pack_f16(pv_[fh][0], pv_[fh][1]);
            Ah_[2 * fh + 1] = pack_f16(pv_[fh][2], pv_[fh][3]);
        }

        mma_f16(lacc, Ah_, ones2);

        int srow = j * 16 + lr16;
        #pragma unroll
        for (int dg = 0; dg < 4; dg++) {
            uint32_t v4[4];
            ldsm_x4_t(v4[0], v4[1], v4[2], v4[3],
                      sbV + (uint32_t)(srow * LDS + dg * 16 + lgo) * 2);
            uint32_t b0[2] = { v4[0], v4[1] };
            uint32_t b1[2] = { v4[2], v4[3] };
            mma_f16(yacc[2 * dg],     Ah_, b0);
            mma_f16(yacc[2 * dg + 1], Ah_, b1);
        }
    }
}

__global__ __launch_bounds__(256, 2)
void attn_mma(const __half* __restrict__ Q, const __half* __restrict__ V,
              const __half* __restrict__ w2t, const float* __restrict__ b2,
              const float* __restrict__ Scs, __half* __restrict__ Yh)
{
    extern __shared__ __half asmem[];
    __half* sQ  = asmem;
    __half* sKV = asmem + ATE;
    float* sb2a   = (float*)(asmem + 5 * ATE);
    float* colacc = sb2a + 1024;

    const uint32_t sbQ  = smem_to_u32(sQ);
    const uint32_t sbKV = smem_to_u32(sKV);

    const int b    = blockIdx.z;
    const int h    = blockIdx.y;
    const int qt   = (int)(gridDim.x - 1) - (int)blockIdx.x;   // heavy first
    const int m0   = qt * 128;
    const int tid  = threadIdx.x;
    const int wid  = tid >> 5;
    const int lane = tid & 31;
    const int mw   = wid * 16;

    const int lrow = tid >> 3;
    const int lc8  = (tid & 7) * 8;

    auto issue_tile = [&](int nt, int buf) {
        const int s0 = nt * 128;
        const uint32_t dK = sbKV + (uint32_t)(buf * 2 * ATE) * 2;
        const uint32_t dV = dK + (uint32_t)ATE * 2;
        #pragma unroll
        for (int i = 0; i < 4; i++) {
            int row = lrow + i * 32;
            uint32_t so = (uint32_t)(row * LDS + lc8) * 2;
            cp16(dK + so, w2t + (size_t)(s0 + row) * DK + lc8);
            int s = s0 + row; if (s > T_SEQ - 1) s = T_SEQ - 1;
            cp16(dV + so, V + ((size_t)b * T_SEQ + s) * C_DIM + h * DK + lc8);
        }
    };

    issue_tile(0, 0);
    CP_COMMIT();

    for (int idx = tid; idx < 1024; idx += 256) {
        int row = idx >> 3, c8 = (idx & 7) * 8;
        int t = m0 + row; if (t > T_SEQ - 1) t = T_SEQ - 1;
        *(uint4*)(sQ + row * LDS + c8) =
            *(const uint4*)(Q + ((size_t)b * T_SEQ + t) * C_DIM + h * DK + c8);
    }
    for (int idx = tid; idx < 1024; idx += 256)
        sb2a[idx] = (idx < T_SEQ) ? b2[idx] * LOG2E : 0.f;
    if (tid < 64) {
        const float* sp = Scs + (((size_t)b * H_NUM + h) * 8) * DK + tid;
        float c = 0.f;
        for (int t = 0; t <= qt; t++) c += sp[t * DK];
        colacc[tid] = c;
    }
    __syncthreads();

    uint32_t qf[4][4];
    {
        int r  = mw + (lane & 15);
        int cg = (lane >> 4) << 3;
        #pragma unroll
        for (int k = 0; k < 4; k++)
            ldsm_x4(qf[k][0], qf[k][1], qf[k][2], qf[k][3],
                    sbQ + (uint32_t)(r * LDS + k * 16 + cg) * 2);
    }

    float yacc[8][4];
    #pragma unroll
    for (int j = 0; j < 8; j++)
        #pragma unroll
        for (int e = 0; e < 4; e++) yacc[j][e] = 0.f;
    float lacc[4] = {0.f, 0.f, 0.f, 0.f};

    const int r0    = lane >> 2;
    const int c0l   = (lane & 3) * 2;
    const int trow0 = m0 + mw + r0;
    const int lgo   = (lane >> 4) << 3;
    const int lr16  = lane & 15;

    for (int nt = 0; nt < qt; nt++) {
        const int p = nt & 1;
        issue_tile(nt + 1, 1 - p);
        CP_COMMIT();
        cp_wait<1>();
        __syncthreads();
        const uint32_t sbK = sbKV + (uint32_t)(p * 2 * ATE) * 2;
        const uint32_t sbV = sbK + (uint32_t)ATE * 2;
        attn_tile<false>(sbK, sbV, nt * 128, sb2a, qf, yacc, lacc,
                         trow0, c0l, lgo, lr16);
        __syncthreads();
    }
    {
        const int p = qt & 1;
        cp_wait<0>();
        __syncthreads();
        const uint32_t sbK = sbKV + (uint32_t)(p * 2 * ATE) * 2;
        const uint32_t sbV = sbK + (uint32_t)ATE * 2;
        attn_tile<true>(sbK, sbV, qt * 128, sb2a, qf, yacc, lacc,
                        trow0, c0l, lgo, lr16);
    }

    const float lbase = 128.f * (float)(qt + 1);
    float inv0 = 1.f / (lbase + lacc[0]);    // row trow0
    float inv1 = 1.f / (lbase + lacc[2]);    // row trow0+8

    #pragma unroll
    for (int half = 0; half < 2; half++) {
        int t = trow0 + half * 8;
        if (t < T_SEQ) {
            float inv = half ? inv1 : inv0;
            size_t base = ((size_t)b * T_SEQ + t) * C_DIM + h * DK;
            #pragma unroll
            for (int j = 0; j < 8; j++) {
                int col = j * 8 + c0l;
                float v0 = (yacc[j][2 * half + 0] + colacc[col])     * inv;
                float v1 = (yacc[j][2 * half + 1] + colacc[col + 1]) * inv;
                __half2 hp;
                hp.x = __float2half_rn(v0); hp.y = __float2half_rn(v1);
                *(__half2*)&Yh[base + col] = hp;
            }
        }
    }
}

// ---------------------------------------------------------------------------
extern "C" void kernel_launch(void* const* d_in, const int* in_sizes, int n_in,
                              void* d_out, int out_size)
{
    const float* x       = (const float*)d_in[0];
    const float* w1_w    = (const float*)d_in[1];
    const float* w1_b    = (const float*)d_in[2];
    const float* w2      = (const float*)d_in[3];
    const float* b2      = (const float*)d_in[4];
    const float* value_w = (const float*)d_in[5];
    const float* value_b = (const float*)d_in[6];
    const float* proj_w  = (const float*)d_in[7];
    const float* proj_b  = (const float*)d_in[8];
    float* out = (float*)d_out;

    __half *xb, *qb, *vs, *yh, *w1s, *vws, *pws, *w2t;
    float* scs;
    cudaGetSymbolAddress((void**)&xb,  g_xb);
    cudaGetSymbolAddress((void**)&qb,  g_qb);  cudaGetSymbolAddress((void**)&vs,  g_vs);
    cudaGetSymbolAddress((void**)&yh,  g_yh);
    cudaGetSymbolAddress((void**)&w1s, g_w1s); cudaGetSymbolAddress((void**)&vws, g_vws);
    cudaGetSymbolAddress((void**)&pws, g_pws); cudaGetSymbolAddress((void**)&w2t, g_w2t);
    cudaGetSymbolAddress((void**)&scs, g_scs);

    cudaFuncSetAttribute(gemm_db<0>, cudaFuncAttributeMaxDynamicSharedMemorySize, GSMEM);
    cudaFuncSetAttribute(gemm_db<1>, cudaFuncAttributeMaxDynamicSharedMemorySize, GSMEM);
    cudaFuncSetAttribute(attn_mma,   cudaFuncAttributeMaxDynamicSharedMemorySize, ASMEM);

    const int NX = R_ROWS * C_DIM;
    const int NW = C_DIM * C_DIM;
    cvt_h<<<NX / 4 / 256, 256>>>(x, xb, NX);
    cvt_h3<<<dim3(NW / 4 / 256, 3), 256>>>(w1_w, value_w, proj_w, w1s, vws, pws);
    prep_w2t<<<(1024 * DK) / 256, 256>>>(w2, w2t);

    // fused relu + value GEMMs: 128x128 CTA, 4 warps of 64x64, 2 CTAs/SM
    gemm_db<1><<<dim3(16, 64), 128, GSMEM>>>(xb, w1s, vws, w1_b, value_b,
                                             nullptr, qb, vs, R_ROWS);

    v_colsum<<<dim3(8, H_NUM, B_SZ), 64>>>(vs, scs);

    attn_mma<<<dim3(8, H_NUM, B_SZ), 256, ASMEM>>>(qb, vs, w2t, b2, scs, yh);

    // projection GEMM, same config
    gemm_db<0><<<dim3(8, 64), 128, GSMEM>>>(yh, pws, nullptr, proj_b, nullptr,
                                            out, nullptr, nullptr, R_ROWS);
}

// round 17
// speedup vs baseline: 1.0653x; 1.0653x over previous
#include <cuda_runtime.h>
#include <cuda_fp16.h>
#include <cstdint>

#define B_SZ   8
#define T_SEQ  1023
#define C_DIM  1024
#define H_NUM  16
#define DK     64
#define R_ROWS (B_SZ * T_SEQ)   // 8184
#define LOG2E  1.4426950408889634f

// ---------------- scratch (__device__ globals: allocation-free contract) ----
__device__ __half g_xb [(size_t)R_ROWS * C_DIM];   // x fp16
__device__ __half g_qb [(size_t)R_ROWS * C_DIM];   // relu_out fp16 (Q)
__device__ __half g_vs [(size_t)R_ROWS * C_DIM];   // value fp16
__device__ __half g_yh [(size_t)R_ROWS * C_DIM];   // attn out fp16
__device__ __half g_w1s[(size_t)C_DIM * C_DIM];
__device__ __half g_vws[(size_t)C_DIM * C_DIM];
__device__ __half g_pws[(size_t)C_DIM * C_DIM];
__device__ __half g_w2t[(size_t)1024 * DK];        // w2^T * log2e, fp16, padded

// ---------------- tensor-core helpers (base-target sm_80+ class) -----------
__device__ __forceinline__ uint32_t smem_to_u32(const void* p) {
    uint32_t a;
    asm("{ .reg .u64 t; cvta.to.shared.u64 t, %1; cvt.u32.u64 %0, t; }"
        : "=r"(a) : "l"(p));
    return a;
}
__device__ __forceinline__ void ldsm_x4(uint32_t& r0, uint32_t& r1,
                                        uint32_t& r2, uint32_t& r3, uint32_t addr) {
    asm volatile("ldmatrix.sync.aligned.m8n8.x4.shared.b16 {%0,%1,%2,%3}, [%4];"
                 : "=r"(r0), "=r"(r1), "=r"(r2), "=r"(r3) : "r"(addr));
}
__device__ __forceinline__ void ldsm_x4_t(uint32_t& r0, uint32_t& r1,
                                          uint32_t& r2, uint32_t& r3, uint32_t addr) {
    asm volatile("ldmatrix.sync.aligned.m8n8.x4.trans.shared.b16 {%0,%1,%2,%3}, [%4];"
                 : "=r"(r0), "=r"(r1), "=r"(r2), "=r"(r3) : "r"(addr));
}
__device__ __forceinline__ void mma_f16(float* c, const uint32_t* a, const uint32_t* b) {
    asm volatile(
        "mma.sync.aligned.m16n8k16.row.col.f32.f16.f16.f32 "
        "{%0,%1,%2,%3}, {%4,%5,%6,%7}, {%8,%9}, {%0,%1,%2,%3};"
        : "+f"(c[0]), "+f"(c[1]), "+f"(c[2]), "+f"(c[3])
        : "r"(a[0]), "r"(a[1]), "r"(a[2]), "r"(a[3]), "r"(b[0]), "r"(b[1]));
}
__device__ __forceinline__ uint32_t pack_f16(float lo, float hi) {
    uint32_t r;
    asm("cvt.rn.f16x2.f32 %0, %1, %2;" : "=r"(r) : "f"(hi), "f"(lo));
    return r;
}
__device__ __forceinline__ float ex2f(float x) {
    float r;
    asm("ex2.approx.f32 %0, %1;" : "=f"(r) : "f"(x));
    return r;
}
__device__ __forceinline__ void cp16(uint32_t saddr, const void* gaddr) {
    asm volatile("cp.async.cg.shared.global [%0], [%1], 16;"
                 :: "r"(saddr), "l"(gaddr));
}
#define CP_COMMIT() asm volatile("cp.async.commit_group;")
template<int N>
__device__ __forceinline__ void cp_wait() {
    asm volatile("cp.async.wait_group %0;" :: "n"(N));
}

// ---------------------------------------------------------------------------
// conversions / prep
// ---------------------------------------------------------------------------
__global__ void cvt_h(const float* __restrict__ in, __half* __restrict__ out, int n)
{
    int i = (blockIdx.x * blockDim.x + threadIdx.x) * 4;
    if (i < n) {
        float4 v = *(const float4*)(in + i);
        __half2 a, b;
        a.x = __float2half_rn(v.x); a.y = __float2half_rn(v.y);
        b.x = __float2half_rn(v.z); b.y = __float2half_rn(v.w);
        *(__half2*)(out + i)     = a;
        *(__half2*)(out + i + 2) = b;
    }
}

__global__ void cvt_h3(const float* __restrict__ i0, const float* __restrict__ i1,
                       const float* __restrict__ i2, __half* __restrict__ o0,
                       __half* __restrict__ o1, __half* __restrict__ o2)
{
    const float* in  = (blockIdx.y == 0) ? i0 : (blockIdx.y == 1) ? i1 : i2;
    __half*      out = (blockIdx.y == 0) ? o0 : (blockIdx.y == 1) ? o1 : o2;
    int i = (blockIdx.x * blockDim.x + threadIdx.x) * 4;
    float4 v = *(const float4*)(in + i);
    __half2 a, b;
    a.x = __float2half_rn(v.x); a.y = __float2half_rn(v.y);
    b.x = __float2half_rn(v.z); b.y = __float2half_rn(v.w);
    *(__half2*)(out + i)     = a;
    *(__half2*)(out + i + 2) = b;
}

// w2 [DK][T_SEQ] f32 -> w2t [1024][DK] fp16, PRESCALED by log2e.
__global__ void prep_w2t(const float* __restrict__ w2, __half* __restrict__ w2t)
{
    int idx = blockIdx.x * 256 + threadIdx.x;     // 1024*64
    int s = idx >> 6, d = idx & 63;
    float v = (s < T_SEQ) ? w2[d * T_SEQ + s] * LOG2E : 0.f;
    w2t[idx] = __float2half_rn(v);
}

// ---------------------------------------------------------------------------
// fp16 HMMA GEMM (R15/R13 config): CTA 128x128, 8 warps 2x4, warp 64x32,
// cp.async double-buffered, occupancy 2.
// ---------------------------------------------------------------------------
#define BM  128
#define BN  128
#define BK  64
#define LDS 72
#define TILE_ELEMS (BM * LDS)
#define GSMEM (4 * TILE_ELEMS * 2)            // 2 x (A + B): 73728 bytes

// MODE 0: f32 out (+bias). MODE 1 (qv-fused): relu->fp16 / plain fp16.
template<int MODE>
__global__ __launch_bounds__(256, 2)
void gemm_db(const __half* __restrict__ A0,
             const __half* __restrict__ B0, const __half* __restrict__ B1,
             const float* __restrict__ bias0, const float* __restrict__ bias1,
             float* __restrict__ Of, __half* __restrict__ O0,
             __half* __restrict__ O1, int R)
{
    extern __shared__ __half sm[];

    const int  tid  = threadIdx.x;
    const int  wid  = tid >> 5;
    const int  lane = tid & 31;
    const int  wm   = wid >> 2;
    const int  wn   = wid & 3;
    const int  m0   = blockIdx.y * BM;
    const bool isQ  = (MODE == 1) && (blockIdx.x < 8);
    const int  n0   = (MODE == 1 ? (isQ ? blockIdx.x : blockIdx.x - 8)
                                 : blockIdx.x) * BN;
    const __half* Bsrc = (MODE == 1) ? (isQ ? B0 : B1) : B0;
    const float*  bias = (MODE == 1) ? (isQ ? bias0 : bias1) : bias0;

    const uint32_t sb = smem_to_u32(sm);
    const int lrow = tid >> 3;          // 0..31
    const int lc8  = (tid & 7) * 8;

    auto issue = [&](int k0, int buf) {
        const uint32_t dA = sb + (uint32_t)(buf * 2 * TILE_ELEMS) * 2;
        const uint32_t dB = dA + (uint32_t)TILE_ELEMS * 2;
        #pragma unroll
        for (int i = 0; i < 4; i++) {
            int row = lrow + i * 32;
            uint32_t so = (uint32_t)(row * LDS + lc8) * 2;
            int ar = m0 + row; if (ar > R - 1) ar = R - 1;   // clamp: epilogue guards
            cp16(dA + so, A0 + (size_t)ar * C_DIM + k0 + lc8);
            cp16(dB + so, Bsrc + (size_t)(n0 + row) * C_DIM + k0 + lc8);
        }
    };

    float acc[4][4][4];
    #pragma unroll
    for (int f = 0; f < 4; f++)
        #pragma unroll
        for (int j = 0; j < 4; j++)
            #pragma unroll
            for (int e = 0; e < 4; e++) acc[f][j][e] = 0.f;

    const int a_r = wm * 64 + (lane & 15);
    const int b_r = wn * 32 + (lane & 15);
    const int l_c = (lane >> 4) << 3;

    issue(0, 0);
    CP_COMMIT();

    for (int kc = 0; kc < C_DIM / BK; kc++) {
        const int p = kc & 1;
        if (kc < C_DIM / BK - 1) {
            issue((kc + 1) * BK, 1 - p);
            CP_COMMIT();
            cp_wait<1>();
        } else {
            cp_wait<0>();
        }
        __syncthreads();

        const uint32_t sbA = sb + (uint32_t)(p * 2 * TILE_ELEMS) * 2;
        const uint32_t sbB = sbA + (uint32_t)TILE_ELEMS * 2;

        #pragma unroll
        for (int kk = 0; kk < BK; kk += 16) {
            uint32_t af[4][4], bh[2][4];
            #pragma unroll
            for (int pp = 0; pp < 2; pp++) {
                uint32_t off = (uint32_t)((b_r + pp * 16) * LDS + kk + l_c) * 2;
                ldsm_x4(bh[pp][0], bh[pp][1], bh[pp][2], bh[pp][3], sbB + off);
            }
            #pragma unroll
            for (int f = 0; f < 4; f++) {
                uint32_t off = (uint32_t)((a_r + f * 16) * LDS + kk + l_c) * 2;
                ldsm_x4(af[f][0], af[f][1], af[f][2], af[f][3], sbA + off);
            }
            #pragma unroll
            for (int f = 0; f < 4; f++)
                #pragma unroll
                for (int j = 0; j < 4; j++) {
                    int pp = j >> 1, hh = j & 1;
                    uint32_t bfr[2] = { bh[pp][hh], bh[pp][2 + hh] };
                    mma_f16(acc[f][j], af[f], bfr);
                }
        }
        __syncthreads();
    }

    const int qr = lane >> 2;
    const int qc = (lane & 3) * 2;
    #pragma unroll
    for (int f = 0; f < 4; f++) {
        #pragma unroll
        for (int j = 0; j < 4; j++) {
            int col = n0 + wn * 32 + j * 8 + qc;
            float b0 = bias[col], b1v = bias[col + 1];
            #pragma unroll
            for (int half = 0; half < 2; half++) {
                int row = m0 + wm * 64 + f * 16 + qr + half * 8;
                if (row < R) {
                    float v0 = acc[f][j][half * 2 + 0] + b0;
                    float v1 = acc[f][j][half * 2 + 1] + b1v;
                    if (MODE == 0) {
                        *(float2*)&Of[(size_t)row * C_DIM + col] = make_float2(v0, v1);
                    } else {
                        if (isQ) { v0 = fmaxf(v0, 0.f); v1 = fmaxf(v1, 0.f); }
                        __half* O = isQ ? O0 : O1;
                        __half2 hp;
                        hp.x = __float2half_rn(v0); hp.y = __float2half_rn(v1);
                        *(__half2*)&O[(size_t)row * C_DIM + col] = hp;
                    }
                }
            }
        }
    }
}

// ---------------------------------------------------------------------------
// HMMA fp16 flash attention v5:
//  - UNCENTERED P: p = ex2(S + b2s) directly (masked -> exactly 0)
//  - no colsum machinery at all; l via ones-column MMA
//  - b2 folded into S-accumulator init, prescaled-log2e, diag split,
//    cp.async double-buffered K/V.
// ---------------------------------------------------------------------------
#define ATE   (128 * LDS)
#define ASMEM (5 * ATE * 2 + 1024 * 4)
#define ONE2  0x3C003C00u                     // fp16 (1.0, 1.0)

template<bool DIAG>
__device__ __forceinline__ void attn_tile(
    uint32_t sbK, uint32_t sbV, int s0, const float* __restrict__ sb2a,
    const uint32_t (&qf)[4][4], float (&yacc)[8][4], float (&lacc)[4],
    int trow0, int c0l, int lgo, int lr16)
{
    const uint32_t ones2[2] = { ONE2, ONE2 };
    #pragma unroll
    for (int j = 0; j < 8; j++) {
        // ---- S accumulators initialized with b2 (bias folded into MMA C) ----
        float Sp[2][4];
        #pragma unroll
        for (int fh = 0; fh < 2; fh++) {
            float2 bb2 = *(const float2*)&sb2a[s0 + 8 * (2 * j + fh) + c0l];
            Sp[fh][0] = bb2.x; Sp[fh][1] = bb2.y;
            Sp[fh][2] = bb2.x; Sp[fh][3] = bb2.y;
        }

        int nr = j * 16 + lr16;
        #pragma unroll
        for (int k = 0; k < 4; k++) {
            uint32_t bb[4];
            ldsm_x4(bb[0], bb[1], bb[2], bb[3],
                    sbK + (uint32_t)(nr * LDS + k * 16 + lgo) * 2);
            uint32_t blo[2] = { bb[0], bb[2] };
            uint32_t bhi[2] = { bb[1], bb[3] };
            mma_f16(Sp[0], qf[k], blo);
            mma_f16(Sp[1], qf[k], bhi);
        }

        // ---- p = ex2(S) (unmasked) / exactly 0 (masked) ----
        float pv_[2][4];
        #pragma unroll
        for (int fh = 0; fh < 2; fh++) {
            if (!DIAG) {
                #pragma unroll
                for (int e = 0; e < 4; e++)
                    pv_[fh][e] = ex2f(Sp[fh][e]);
            } else {
                int f = 2 * j + fh;
                #pragma unroll
                for (int e = 0; e < 4; e++) {
                    int col = 8 * f + c0l + (e & 1);
                    int rr  = trow0 + ((e >> 1) << 3);
                    bool ok = (s0 + col <= rr);
                    pv_[fh][e] = ok ? ex2f(Sp[fh][e]) : 0.f;
                }
            }
        }

        uint32_t Ah_[4];
        #pragma unroll
        for (int fh = 0; fh < 2; fh++) {
            Ah_[2 * fh + 0] = pack_f16(pv_[fh][0], pv_[fh][1]);
            Ah_[2 * fh + 1] = pack_f16(pv_[fh][2], pv_[fh][3]);
        }

        // row-sum of packed P via ones-MMA (all 8 out-cols identical)
        mma_f16(lacc, Ah_, ones2);

        int srow = j * 16 + lr16;
        #pragma unroll
        for (int dg = 0; dg < 4; dg++) {
            uint32_t v4[4];
            ldsm_x4_t(v4[0], v4[1], v4[2], v4[3],
                      sbV + (uint32_t)(srow * LDS + dg * 16 + lgo) * 2);
            uint32_t b0[2] = { v4[0], v4[1] };
            uint32_t b1[2] = { v4[2], v4[3] };
            mma_f16(yacc[2 * dg],     Ah_, b0);
            mma_f16(yacc[2 * dg + 1], Ah_, b1);
        }
    }
}

__global__ __launch_bounds__(256, 2)
void attn_mma(const __half* __restrict__ Q, const __half* __restrict__ V,
              const __half* __restrict__ w2t, const float* __restrict__ b2,
              __half* __restrict__ Yh)
{
    extern __shared__ __half asmem[];
    __half* sQ  = asmem;
    __half* sKV = asmem + ATE;
    float* sb2a = (float*)(asmem + 5 * ATE);

    const uint32_t sbQ  = smem_to_u32(sQ);
    const uint32_t sbKV = smem_to_u32(sKV);

    const int b    = blockIdx.z;
    const int h    = blockIdx.y;
    const int qt   = (int)(gridDim.x - 1) - (int)blockIdx.x;   // heavy first
    const int m0   = qt * 128;
    const int tid  = threadIdx.x;
    const int wid  = tid >> 5;
    const int lane = tid & 31;
    const int mw   = wid * 16;

    const int lrow = tid >> 3;
    const int lc8  = (tid & 7) * 8;

    auto issue_tile = [&](int nt, int buf) {
        const int s0 = nt * 128;
        const uint32_t dK = sbKV + (uint32_t)(buf * 2 * ATE) * 2;
        const uint32_t dV = dK + (uint32_t)ATE * 2;
        #pragma unroll
        for (int i = 0; i < 4; i++) {
            int row = lrow + i * 32;
            uint32_t so = (uint32_t)(row * LDS + lc8) * 2;
            cp16(dK + so, w2t + (size_t)(s0 + row) * DK + lc8);
            int s = s0 + row; if (s > T_SEQ - 1) s = T_SEQ - 1;
            cp16(dV + so, V + ((size_t)b * T_SEQ + s) * C_DIM + h * DK + lc8);
        }
    };

    issue_tile(0, 0);
    CP_COMMIT();

    for (int idx = tid; idx < 1024; idx += 256) {
        int row = idx >> 3, c8 = (idx & 7) * 8;
        int t = m0 + row; if (t > T_SEQ - 1) t = T_SEQ - 1;
        *(uint4*)(sQ + row * LDS + c8) =
            *(const uint4*)(Q + ((size_t)b * T_SEQ + t) * C_DIM + h * DK + c8);
    }
    for (int idx = tid; idx < 1024; idx += 256)
        sb2a[idx] = (idx < T_SEQ) ? b2[idx] * LOG2E : 0.f;
    __syncthreads();

    uint32_t qf[4][4];
    {
        int r  = mw + (lane & 15);
        int cg = (lane >> 4) << 3;
        #pragma unroll
        for (int k = 0; k < 4; k++)
            ldsm_x4(qf[k][0], qf[k][1], qf[k][2], qf[k][3],
                    sbQ + (uint32_t)(r * LDS + k * 16 + cg) * 2);
    }

    float yacc[8][4];
    #pragma unroll
    for (int j = 0; j < 8; j++)
        #pragma unroll
        for (int e = 0; e < 4; e++) yacc[j][e] = 0.f;
    float lacc[4] = {0.f, 0.f, 0.f, 0.f};

    const int r0    = lane >> 2;
    const int c0l   = (lane & 3) * 2;
    const int trow0 = m0 + mw + r0;
    const int lgo   = (lane >> 4) << 3;
    const int lr16  = lane & 15;

    for (int nt = 0; nt < qt; nt++) {
        const int p = nt & 1;
        issue_tile(nt + 1, 1 - p);
        CP_COMMIT();
        cp_wait<1>();
        __syncthreads();
        const uint32_t sbK = sbKV + (uint32_t)(p * 2 * ATE) * 2;
        const uint32_t sbV = sbK + (uint32_t)ATE * 2;
        attn_tile<false>(sbK, sbV, nt * 128, sb2a, qf, yacc, lacc,
                         trow0, c0l, lgo, lr16);
        __syncthreads();
    }
    {
        const int p = qt & 1;
        cp_wait<0>();
        __syncthreads();
        const uint32_t sbK = sbKV + (uint32_t)(p * 2 * ATE) * 2;
        const uint32_t sbV = sbK + (uint32_t)ATE * 2;
        attn_tile<true>(sbK, sbV, qt * 128, sb2a, qf, yacc, lacc,
                        trow0, c0l, lgo, lr16);
    }

    float inv0 = 1.f / lacc[0];    // row trow0
    float inv1 = 1.f / lacc[2];    // row trow0+8

    #pragma unroll
    for (int half = 0; half < 2; half++) {
        int t = trow0 + half * 8;
        if (t < T_SEQ) {
            float inv = half ? inv1 : inv0;
            size_t base = ((size_t)b * T_SEQ + t) * C_DIM + h * DK;
            #pragma unroll
            for (int j = 0; j < 8; j++) {
                int col = j * 8 + c0l;
                float v0 = yacc[j][2 * half + 0] * inv;
                float v1 = yacc[j][2 * half + 1] * inv;
                __half2 hp;
                hp.x = __float2half_rn(v0); hp.y = __float2half_rn(v1);
                *(__half2*)&Yh[base + col] = hp;
            }
        }
    }
}

// ---------------------------------------------------------------------------
extern "C" void kernel_launch(void* const* d_in, const int* in_sizes, int n_in,
                              void* d_out, int out_size)
{
    const float* x       = (const float*)d_in[0];
    const float* w1_w    = (const float*)d_in[1];
    const float* w1_b    = (const float*)d_in[2];
    const float* w2      = (const float*)d_in[3];
    const float* b2      = (const float*)d_in[4];
    const float* value_w = (const float*)d_in[5];
    const float* value_b = (const float*)d_in[6];
    const float* proj_w  = (const float*)d_in[7];
    const float* proj_b  = (const float*)d_in[8];
    float* out = (float*)d_out;

    __half *xb, *qb, *vs, *yh, *w1s, *vws, *pws, *w2t;
    cudaGetSymbolAddress((void**)&xb,  g_xb);
    cudaGetSymbolAddress((void**)&qb,  g_qb);  cudaGetSymbolAddress((void**)&vs,  g_vs);
    cudaGetSymbolAddress((void**)&yh,  g_yh);
    cudaGetSymbolAddress((void**)&w1s, g_w1s); cudaGetSymbolAddress((void**)&vws, g_vws);
    cudaGetSymbolAddress((void**)&pws, g_pws); cudaGetSymbolAddress((void**)&w2t, g_w2t);

    cudaFuncSetAttribute(gemm_db<0>, cudaFuncAttributeMaxDynamicSharedMemorySize, GSMEM);
    cudaFuncSetAttribute(gemm_db<1>, cudaFuncAttributeMaxDynamicSharedMemorySize, GSMEM);
    cudaFuncSetAttribute(attn_mma,   cudaFuncAttributeMaxDynamicSharedMemorySize, ASMEM);

    const int NX = R_ROWS * C_DIM;
    const int NW = C_DIM * C_DIM;
    cvt_h<<<NX / 4 / 256, 256>>>(x, xb, NX);
    cvt_h3<<<dim3(NW / 4 / 256, 3), 256>>>(w1_w, value_w, proj_w, w1s, vws, pws);
    prep_w2t<<<(1024 * DK) / 256, 256>>>(w2, w2t);

    // fused relu + value GEMMs (R15 config), double-buffered
    gemm_db<1><<<dim3(16, 64), 256, GSMEM>>>(xb, w1s, vws, w1_b, value_b,
                                             nullptr, qb, vs, R_ROWS);

    attn_mma<<<dim3(8, H_NUM, B_SZ), 256, ASMEM>>>(qb, vs, w2t, b2, yh);

    // projection GEMM (R15 config), double-buffered
    gemm_db<0><<<dim3(8, 64), 256, GSMEM>>>(yh, pws, nullptr, proj_b, nullptr,
                                            out, nullptr, nullptr, R_ROWS);
}